// round 12
// baseline (speedup 1.0000x reference)
#include <cuda_runtime.h>
#include <cuda_fp16.h>
#include <cstdint>

#define NUM_USERS 100000
#define NUM_ITEMS 50000
#define N_NODES   150000
#define EMB_D     64
#define NUM_EDGES 2000000
#define N_DIRECTED (2 * NUM_EDGES)               // 4M real adjacency entries
#define N_PAD (N_DIRECTED + 3 * N_NODES)         // padded upper bound
#define N_PAD4 ((N_PAD + 3) / 4)
#define N_ROWH2  ((N_NODES + 1) * (EMB_D / 2))   // +1 dummy zero row

#define BUILD_BLOCKS  148
#define BUILD_THREADS 1024
#define BUILD_NTHREADS (BUILD_BLOCKS * BUILD_THREADS)   // 151552 >= N_NODES

// Scratch (device globals; zero-initialized, no allocation allowed).
__device__ __half2 g_buf0h[N_ROWH2];             // 19.2 MB fp16 embeddings
__device__ __half2 g_buf1h[N_ROWH2];             // 19.2 MB layer-1 out
__device__ int     g_deg[N_NODES];
__device__ int     g_off[N_NODES];
__device__ int     g_cursor[N_NODES];
__device__ int     g_blocksum[BUILD_BLOCKS];
__device__ uint4   g_adj4[N_PAD4];               // adjacency, 16B-aligned
__device__ unsigned g_bar_count;                 // software grid barrier
__device__ unsigned g_bar_gen;                   // generation (monotonic)

// ---------------------------------------------------------------------------
// Software grid barrier. Safe because all BUILD_BLOCKS are co-resident
// (148 blocks of 1024 threads on a 148+-SM chip). Generation counter is
// monotonic so state is consistent across graph replays.
// ---------------------------------------------------------------------------
__device__ __forceinline__ void grid_barrier() {
    __syncthreads();
    if (threadIdx.x == 0) {
        volatile unsigned* genp = &g_bar_gen;
        unsigned gen = *genp;
        __threadfence();
        unsigned ticket = atomicInc(&g_bar_count, BUILD_BLOCKS - 1);
        if (ticket == BUILD_BLOCKS - 1) {
            atomicAdd(&g_bar_gen, 1u);           // release (count auto-wrapped)
        } else {
            while (*genp == gen) { }
        }
        __threadfence();
    }
    __syncthreads();
}

// ---------------------------------------------------------------------------
// Fused build: embed copy + deg zero -> hist -> scan -> cursors/padding -> fill
// One launch replaces six.
// ---------------------------------------------------------------------------
__global__ void __launch_bounds__(BUILD_THREADS, 1)
build_kernel(const float4* __restrict__ user4,
             const float4* __restrict__ item4,
             const int4* __restrict__ erow4,
             const int4* __restrict__ ecol4) {
    const int tid = threadIdx.x;
    const int gid = blockIdx.x * BUILD_THREADS + tid;

    // ---- Phase 1: embed convert-copy + zero degree counters + dummy rows
    {
        const int total4 = N_NODES * (EMB_D / 4);      // 2.4M
        const int user4n = NUM_USERS * (EMB_D / 4);    // 1.6M
        for (int i = gid; i < total4; i += BUILD_NTHREADS) {
            float4 v = (i < user4n) ? user4[i] : item4[i - user4n];
            g_buf0h[2 * i + 0] = __floats2half2_rn(v.x, v.y);
            g_buf0h[2 * i + 1] = __floats2half2_rn(v.z, v.w);
        }
        if (gid < N_NODES) g_deg[gid] = 0;
        if (gid < EMB_D / 2) {
            g_buf0h[(size_t)N_NODES * 32 + gid] = __floats2half2_rn(0.f, 0.f);
            g_buf1h[(size_t)N_NODES * 32 + gid] = __floats2half2_rn(0.f, 0.f);
        }
    }
    grid_barrier();

    // ---- Phase 2: degree histogram (4 edges per int4 pair)
    for (int i = gid; i < NUM_EDGES / 4; i += BUILD_NTHREADS) {
        int4 r = erow4[i];
        int4 c = ecol4[i];
        atomicAdd(&g_deg[r.x], 1); atomicAdd(&g_deg[r.y], 1);
        atomicAdd(&g_deg[r.z], 1); atomicAdd(&g_deg[r.w], 1);
        atomicAdd(&g_deg[c.x], 1); atomicAdd(&g_deg[c.y], 1);
        atomicAdd(&g_deg[c.z], 1); atomicAdd(&g_deg[c.w], 1);
    }
    grid_barrier();

    // ---- Phase 3: exclusive scan of padded degrees (one node per thread)
    __shared__ int sh[BUILD_THREADS];
    __shared__ int sh_base;
    int myDeg = 0, myPad = 0;
    if (gid < N_NODES) {
        myDeg = g_deg[gid];
        myPad = (myDeg + 3) & ~3;
    }
    sh[tid] = myPad;
    __syncthreads();
    for (int ofs = 1; ofs < BUILD_THREADS; ofs <<= 1) {
        int x = (tid >= ofs) ? sh[tid - ofs] : 0;
        __syncthreads();
        sh[tid] += x;
        __syncthreads();
    }
    int excl = sh[tid] - myPad;                    // exclusive within block
    if (tid == BUILD_THREADS - 1) g_blocksum[blockIdx.x] = sh[tid];
    grid_barrier();

    // per-block base: redundant serial sum of 148 block sums (cheap)
    if (tid == 0) {
        int s = 0;
        for (int b = 0; b < (int)blockIdx.x; b++) s += g_blocksum[b];
        sh_base = s;
    }
    __syncthreads();

    if (gid < N_NODES) {
        int o = sh_base + excl;
        g_off[gid]    = o;
        g_cursor[gid] = o;
        int* adj = reinterpret_cast<int*>(g_adj4);
        for (int p = myDeg; p < myPad; p++) adj[o + p] = N_NODES;  // dummy
    }
    grid_barrier();

    // ---- Phase 4: CSR fill
    {
        int* adj = reinterpret_cast<int*>(g_adj4);
        for (int i = gid; i < NUM_EDGES / 4; i += BUILD_NTHREADS) {
            int4 r = erow4[i];
            int4 c = ecol4[i];
            adj[atomicAdd(&g_cursor[r.x], 1)] = c.x;
            adj[atomicAdd(&g_cursor[c.x], 1)] = r.x;
            adj[atomicAdd(&g_cursor[r.y], 1)] = c.y;
            adj[atomicAdd(&g_cursor[c.y], 1)] = r.y;
            adj[atomicAdd(&g_cursor[r.z], 1)] = c.z;
            adj[atomicAdd(&g_cursor[c.z], 1)] = r.z;
            adj[atomicAdd(&g_cursor[r.w], 1)] = c.w;
            adj[atomicAdd(&g_cursor[c.w], 1)] = r.w;
        }
    }
}

// ---------------------------------------------------------------------------
// Packed pull: one warp per node; each gather LDG.128 fetches FOUR neighbor
// rows (8 lanes x 16B each). fp32 accum; shfl combine.
// ---------------------------------------------------------------------------
__device__ __forceinline__ void pull_accum(const __half2* __restrict__ src,
                                           int start, int d, int lane,
                                           float acc[8]) {
    const uint4* __restrict__ adj4 =
        reinterpret_cast<const uint4*>(g_adj4) + (start >> 2);
    int n4 = (d + 3) >> 2;
    int q   = lane >> 3;
    int sub = lane & 7;

    const char* base = reinterpret_cast<const char*>(src);

    int j = 0;
    for (; j + 8 <= n4; j += 8) {
#pragma unroll
        for (int k = 0; k < 8; k++) {
            uint4 av = adj4[j + k];
            int u = (q == 0) ? (int)av.x : (q == 1) ? (int)av.y
                  : (q == 2) ? (int)av.z : (int)av.w;
            uint4 row = *reinterpret_cast<const uint4*>(
                base + (size_t)u * 128 + sub * 16);
            const __half2* h = reinterpret_cast<const __half2*>(&row);
            float2 f0 = __half22float2(h[0]);
            float2 f1 = __half22float2(h[1]);
            float2 f2 = __half22float2(h[2]);
            float2 f3 = __half22float2(h[3]);
            acc[0] += f0.x; acc[1] += f0.y;
            acc[2] += f1.x; acc[3] += f1.y;
            acc[4] += f2.x; acc[5] += f2.y;
            acc[6] += f3.x; acc[7] += f3.y;
        }
    }
    for (; j < n4; j++) {
        uint4 av = adj4[j];
        int u = (q == 0) ? (int)av.x : (q == 1) ? (int)av.y
              : (q == 2) ? (int)av.z : (int)av.w;
        uint4 row = *reinterpret_cast<const uint4*>(
            base + (size_t)u * 128 + sub * 16);
        const __half2* h = reinterpret_cast<const __half2*>(&row);
        float2 f0 = __half22float2(h[0]);
        float2 f1 = __half22float2(h[1]);
        float2 f2 = __half22float2(h[2]);
        float2 f3 = __half22float2(h[3]);
        acc[0] += f0.x; acc[1] += f0.y;
        acc[2] += f1.x; acc[3] += f1.y;
        acc[4] += f2.x; acc[5] += f2.y;
        acc[6] += f3.x; acc[7] += f3.y;
    }

#pragma unroll
    for (int i = 0; i < 8; i++) {
        acc[i] += __shfl_xor_sync(0xFFFFFFFFu, acc[i], 8);
        acc[i] += __shfl_xor_sync(0xFFFFFFFFu, acc[i], 16);
    }
}

// pull layer 1: buf1h[v] = half(0.5 * sum buf0h[adj])
__global__ void pull1_kernel() {
    int gwarp = (blockIdx.x * blockDim.x + threadIdx.x) >> 5;
    if (gwarp >= N_NODES) return;
    int lane = threadIdx.x & 31;
    float acc[8] = {0.f, 0.f, 0.f, 0.f, 0.f, 0.f, 0.f, 0.f};
    pull_accum(g_buf0h, g_off[gwarp], g_deg[gwarp], lane, acc);
    if (lane < 8) {
        uint4 o;
        __half2 h0 = __floats2half2_rn(0.5f * acc[0], 0.5f * acc[1]);
        __half2 h1 = __floats2half2_rn(0.5f * acc[2], 0.5f * acc[3]);
        __half2 h2 = __floats2half2_rn(0.5f * acc[4], 0.5f * acc[5]);
        __half2 h3 = __floats2half2_rn(0.5f * acc[6], 0.5f * acc[7]);
        o.x = *reinterpret_cast<unsigned*>(&h0);
        o.y = *reinterpret_cast<unsigned*>(&h1);
        o.z = *reinterpret_cast<unsigned*>(&h2);
        o.w = *reinterpret_cast<unsigned*>(&h3);
        *reinterpret_cast<uint4*>(
            reinterpret_cast<char*>(g_buf1h) + (size_t)gwarp * 128 + lane * 16) = o;
    }
}

// pull layer 2: out[v] = 0.5 * sum buf1h[adj]  (f32 output)
__global__ void pull2_kernel(float* __restrict__ out) {
    int gwarp = (blockIdx.x * blockDim.x + threadIdx.x) >> 5;
    if (gwarp >= N_NODES) return;
    int lane = threadIdx.x & 31;
    float acc[8] = {0.f, 0.f, 0.f, 0.f, 0.f, 0.f, 0.f, 0.f};
    pull_accum(g_buf1h, g_off[gwarp], g_deg[gwarp], lane, acc);
    if (lane < 8) {
        float* dp = out + (size_t)gwarp * EMB_D + lane * 8;
        float4 a = make_float4(0.5f * acc[0], 0.5f * acc[1],
                               0.5f * acc[2], 0.5f * acc[3]);
        float4 b = make_float4(0.5f * acc[4], 0.5f * acc[5],
                               0.5f * acc[6], 0.5f * acc[7]);
        *reinterpret_cast<float4*>(dp)     = a;
        *reinterpret_cast<float4*>(dp + 4) = b;
    }
}

// ---------------------------------------------------------------------------
extern "C" void kernel_launch(void* const* d_in, const int* in_sizes, int n_in,
                              void* d_out, int out_size) {
    const int*   edge_index = (const int*)d_in[0];   // [2, E] int32
    const float* user_emb   = (const float*)d_in[1];
    const float* item_emb   = (const float*)d_in[2];
    float*       out        = (float*)d_out;

    const int4* erow4 = (const int4*)edge_index;
    const int4* ecol4 = (const int4*)(edge_index + NUM_EDGES);

    // fused build: init + hist + scan + fill in one persistent launch
    build_kernel<<<BUILD_BLOCKS, BUILD_THREADS>>>(
        (const float4*)user_emb, (const float4*)item_emb, erow4, ecol4);

    // two pull layers
    {
        long long total_threads = (long long)N_NODES * 32;
        int threads = 256;
        int blocks  = (int)((total_threads + threads - 1) / threads);
        pull1_kernel<<<blocks, threads>>>();
        pull2_kernel<<<blocks, threads>>>(out);
    }
}

// round 13
// speedup vs baseline: 1.0547x; 1.0547x over previous
#include <cuda_runtime.h>
#include <cuda_fp16.h>
#include <cstdint>

#define NUM_USERS 100000
#define NUM_ITEMS 50000
#define N_NODES   150000
#define EMB_D     64
#define NUM_EDGES 2000000
#define N_DIRECTED (2 * NUM_EDGES)               // 4M real adjacency entries
#define N_PAD (N_DIRECTED + 3 * N_NODES)         // padded upper bound
#define N_PAD4 ((N_PAD + 3) / 4)
#define N_ROWH2  ((N_NODES + 1) * (EMB_D / 2))   // +1 dummy zero row

#define BUILD_BLOCKS  148
#define BUILD_THREADS 1024
#define BUILD_NTHREADS (BUILD_BLOCKS * BUILD_THREADS)   // 151552 >= N_NODES

// Scratch (device globals; no allocation allowed).
__device__ __half2 g_buf0h[N_ROWH2];             // 19.2 MB fp16 embeddings
__device__ __half2 g_buf1h[N_ROWH2];             // 19.2 MB layer-1 out
__device__ int     g_deg[N_NODES];
__device__ int     g_off[N_NODES];
__device__ int     g_rankR[NUM_EDGES];           // 8 MB: rank of edge at row end
__device__ int     g_rankC[NUM_EDGES];           // 8 MB: rank of edge at col end
__device__ int     g_blocksum[BUILD_BLOCKS];
__device__ uint4   g_adj4[N_PAD4];               // adjacency, 16B-aligned
__device__ unsigned g_bar_count;                 // software grid barrier
__device__ unsigned g_bar_gen;                   // generation (monotonic)

// ---------------------------------------------------------------------------
// Software grid barrier (all BUILD_BLOCKS co-resident; monotonic generation
// so state is consistent across graph replays).
// ---------------------------------------------------------------------------
__device__ __forceinline__ void grid_barrier() {
    __syncthreads();
    if (threadIdx.x == 0) {
        volatile unsigned* genp = &g_bar_gen;
        unsigned gen = *genp;
        __threadfence();
        unsigned ticket = atomicInc(&g_bar_count, BUILD_BLOCKS - 1);
        if (ticket == BUILD_BLOCKS - 1) {
            atomicAdd(&g_bar_gen, 1u);
        } else {
            while (*genp == gen) { }
        }
        __threadfence();
    }
    __syncthreads();
}

// ---------------------------------------------------------------------------
// Fused build, rank-recording variant:
//   P1: zero degree counters (+ dummy rows)
//   P2: histogram WITH rank capture (atomic return value = rank) + embed
//       convert-copy (independent; its bandwidth hides under atomic latency)
//   P3: scan of padded degrees -> offsets; write padding entries
//   P4: atomic-FREE fill: adj[off[node] + rank] = neighbor
// ---------------------------------------------------------------------------
__global__ void __launch_bounds__(BUILD_THREADS, 1)
build_kernel(const float4* __restrict__ user4,
             const float4* __restrict__ item4,
             const int4* __restrict__ erow4,
             const int4* __restrict__ ecol4) {
    const int tid = threadIdx.x;
    const int gid = blockIdx.x * BUILD_THREADS + tid;

    // ---- P1: zero degree counters + dummy rows
    if (gid < N_NODES) g_deg[gid] = 0;
    if (gid < EMB_D / 2) {
        g_buf0h[(size_t)N_NODES * 32 + gid] = __floats2half2_rn(0.f, 0.f);
        g_buf1h[(size_t)N_NODES * 32 + gid] = __floats2half2_rn(0.f, 0.f);
    }
    grid_barrier();

    // ---- P2: histogram with rank capture, then embed copy (independent)
    {
        int4* rankR4 = reinterpret_cast<int4*>(g_rankR);
        int4* rankC4 = reinterpret_cast<int4*>(g_rankC);
        for (int i = gid; i < NUM_EDGES / 4; i += BUILD_NTHREADS) {
            int4 r = erow4[i];
            int4 c = ecol4[i];
            int4 rr, rc;
            rr.x = atomicAdd(&g_deg[r.x], 1);
            rc.x = atomicAdd(&g_deg[c.x], 1);
            rr.y = atomicAdd(&g_deg[r.y], 1);
            rc.y = atomicAdd(&g_deg[c.y], 1);
            rr.z = atomicAdd(&g_deg[r.z], 1);
            rc.z = atomicAdd(&g_deg[c.z], 1);
            rr.w = atomicAdd(&g_deg[r.w], 1);
            rc.w = atomicAdd(&g_deg[c.w], 1);
            rankR4[i] = rr;
            rankC4[i] = rc;
        }

        const int total4 = N_NODES * (EMB_D / 4);      // 2.4M
        const int user4n = NUM_USERS * (EMB_D / 4);    // 1.6M
        for (int i = gid; i < total4; i += BUILD_NTHREADS) {
            float4 v = (i < user4n) ? user4[i] : item4[i - user4n];
            g_buf0h[2 * i + 0] = __floats2half2_rn(v.x, v.y);
            g_buf0h[2 * i + 1] = __floats2half2_rn(v.z, v.w);
        }
    }
    grid_barrier();

    // ---- P3: exclusive scan of padded degrees (one node per thread)
    __shared__ int sh[BUILD_THREADS];
    __shared__ int sh_base;
    int myDeg = 0, myPad = 0;
    if (gid < N_NODES) {
        myDeg = g_deg[gid];
        myPad = (myDeg + 3) & ~3;
    }
    sh[tid] = myPad;
    __syncthreads();
    for (int ofs = 1; ofs < BUILD_THREADS; ofs <<= 1) {
        int x = (tid >= ofs) ? sh[tid - ofs] : 0;
        __syncthreads();
        sh[tid] += x;
        __syncthreads();
    }
    int excl = sh[tid] - myPad;
    if (tid == BUILD_THREADS - 1) g_blocksum[blockIdx.x] = sh[tid];
    grid_barrier();

    if (tid == 0) {
        int s = 0;
        for (int b = 0; b < (int)blockIdx.x; b++) s += g_blocksum[b];
        sh_base = s;
    }
    __syncthreads();

    if (gid < N_NODES) {
        int o = sh_base + excl;
        g_off[gid] = o;
        int* adj = reinterpret_cast<int*>(g_adj4);
        for (int p = myDeg; p < myPad; p++) adj[o + p] = N_NODES;  // dummy
    }
    grid_barrier();

    // ---- P4: atomic-free CSR fill via recorded ranks
    {
        int* adj = reinterpret_cast<int*>(g_adj4);
        const int4* rankR4 = reinterpret_cast<const int4*>(g_rankR);
        const int4* rankC4 = reinterpret_cast<const int4*>(g_rankC);
        for (int i = gid; i < NUM_EDGES / 4; i += BUILD_NTHREADS) {
            int4 r  = erow4[i];
            int4 c  = ecol4[i];
            int4 rr = rankR4[i];
            int4 rc = rankC4[i];
            adj[g_off[r.x] + rr.x] = c.x;
            adj[g_off[c.x] + rc.x] = r.x;
            adj[g_off[r.y] + rr.y] = c.y;
            adj[g_off[c.y] + rc.y] = r.y;
            adj[g_off[r.z] + rr.z] = c.z;
            adj[g_off[c.z] + rc.z] = r.z;
            adj[g_off[r.w] + rr.w] = c.w;
            adj[g_off[c.w] + rc.w] = r.w;
        }
    }
}

// ---------------------------------------------------------------------------
// Packed pull: one warp per node; each gather LDG.128 fetches FOUR neighbor
// rows (8 lanes x 16B each). fp32 accum; shfl combine.
// ---------------------------------------------------------------------------
__device__ __forceinline__ void pull_accum(const __half2* __restrict__ src,
                                           int start, int d, int lane,
                                           float acc[8]) {
    const uint4* __restrict__ adj4 =
        reinterpret_cast<const uint4*>(g_adj4) + (start >> 2);
    int n4 = (d + 3) >> 2;
    int q   = lane >> 3;
    int sub = lane & 7;

    const char* base = reinterpret_cast<const char*>(src);

    int j = 0;
    for (; j + 8 <= n4; j += 8) {
#pragma unroll
        for (int k = 0; k < 8; k++) {
            uint4 av = adj4[j + k];
            int u = (q == 0) ? (int)av.x : (q == 1) ? (int)av.y
                  : (q == 2) ? (int)av.z : (int)av.w;
            uint4 row = *reinterpret_cast<const uint4*>(
                base + (size_t)u * 128 + sub * 16);
            const __half2* h = reinterpret_cast<const __half2*>(&row);
            float2 f0 = __half22float2(h[0]);
            float2 f1 = __half22float2(h[1]);
            float2 f2 = __half22float2(h[2]);
            float2 f3 = __half22float2(h[3]);
            acc[0] += f0.x; acc[1] += f0.y;
            acc[2] += f1.x; acc[3] += f1.y;
            acc[4] += f2.x; acc[5] += f2.y;
            acc[6] += f3.x; acc[7] += f3.y;
        }
    }
    for (; j < n4; j++) {
        uint4 av = adj4[j];
        int u = (q == 0) ? (int)av.x : (q == 1) ? (int)av.y
              : (q == 2) ? (int)av.z : (int)av.w;
        uint4 row = *reinterpret_cast<const uint4*>(
            base + (size_t)u * 128 + sub * 16);
        const __half2* h = reinterpret_cast<const __half2*>(&row);
        float2 f0 = __half22float2(h[0]);
        float2 f1 = __half22float2(h[1]);
        float2 f2 = __half22float2(h[2]);
        float2 f3 = __half22float2(h[3]);
        acc[0] += f0.x; acc[1] += f0.y;
        acc[2] += f1.x; acc[3] += f1.y;
        acc[4] += f2.x; acc[5] += f2.y;
        acc[6] += f3.x; acc[7] += f3.y;
    }

#pragma unroll
    for (int i = 0; i < 8; i++) {
        acc[i] += __shfl_xor_sync(0xFFFFFFFFu, acc[i], 8);
        acc[i] += __shfl_xor_sync(0xFFFFFFFFu, acc[i], 16);
    }
}

// pull layer 1: buf1h[v] = half(0.5 * sum buf0h[adj])
__global__ void pull1_kernel() {
    int gwarp = (blockIdx.x * blockDim.x + threadIdx.x) >> 5;
    if (gwarp >= N_NODES) return;
    int lane = threadIdx.x & 31;
    float acc[8] = {0.f, 0.f, 0.f, 0.f, 0.f, 0.f, 0.f, 0.f};
    pull_accum(g_buf0h, g_off[gwarp], g_deg[gwarp], lane, acc);
    if (lane < 8) {
        uint4 o;
        __half2 h0 = __floats2half2_rn(0.5f * acc[0], 0.5f * acc[1]);
        __half2 h1 = __floats2half2_rn(0.5f * acc[2], 0.5f * acc[3]);
        __half2 h2 = __floats2half2_rn(0.5f * acc[4], 0.5f * acc[5]);
        __half2 h3 = __floats2half2_rn(0.5f * acc[6], 0.5f * acc[7]);
        o.x = *reinterpret_cast<unsigned*>(&h0);
        o.y = *reinterpret_cast<unsigned*>(&h1);
        o.z = *reinterpret_cast<unsigned*>(&h2);
        o.w = *reinterpret_cast<unsigned*>(&h3);
        *reinterpret_cast<uint4*>(
            reinterpret_cast<char*>(g_buf1h) + (size_t)gwarp * 128 + lane * 16) = o;
    }
}

// pull layer 2: out[v] = 0.5 * sum buf1h[adj]  (f32 output)
__global__ void pull2_kernel(float* __restrict__ out) {
    int gwarp = (blockIdx.x * blockDim.x + threadIdx.x) >> 5;
    if (gwarp >= N_NODES) return;
    int lane = threadIdx.x & 31;
    float acc[8] = {0.f, 0.f, 0.f, 0.f, 0.f, 0.f, 0.f, 0.f};
    pull_accum(g_buf1h, g_off[gwarp], g_deg[gwarp], lane, acc);
    if (lane < 8) {
        float* dp = out + (size_t)gwarp * EMB_D + lane * 8;
        float4 a = make_float4(0.5f * acc[0], 0.5f * acc[1],
                               0.5f * acc[2], 0.5f * acc[3]);
        float4 b = make_float4(0.5f * acc[4], 0.5f * acc[5],
                               0.5f * acc[6], 0.5f * acc[7]);
        *reinterpret_cast<float4*>(dp)     = a;
        *reinterpret_cast<float4*>(dp + 4) = b;
    }
}

// ---------------------------------------------------------------------------
extern "C" void kernel_launch(void* const* d_in, const int* in_sizes, int n_in,
                              void* d_out, int out_size) {
    const int*   edge_index = (const int*)d_in[0];   // [2, E] int32
    const float* user_emb   = (const float*)d_in[1];
    const float* item_emb   = (const float*)d_in[2];
    float*       out        = (float*)d_out;

    const int4* erow4 = (const int4*)edge_index;
    const int4* ecol4 = (const int4*)(edge_index + NUM_EDGES);

    // fused build (zero -> hist+rank+copy -> scan -> atomic-free fill)
    build_kernel<<<BUILD_BLOCKS, BUILD_THREADS>>>(
        (const float4*)user_emb, (const float4*)item_emb, erow4, ecol4);

    // two pull layers
    {
        long long total_threads = (long long)N_NODES * 32;
        int threads = 256;
        int blocks  = (int)((total_threads + threads - 1) / threads);
        pull1_kernel<<<blocks, threads>>>();
        pull2_kernel<<<blocks, threads>>>(out);
    }
}